// round 5
// baseline (speedup 1.0000x reference)
#include <cuda_runtime.h>
#include <cstddef>

#define NN 13
#define DD 16
#define EPB 24
#define EPT 3
#define NTHREADS 128
#define NLAYERS 4
#define NCH 4
#define BN_EPS 1e-5f
#define ADJF 676   /* 4*13*13 floats per element */

typedef unsigned long long u64;

__device__ __forceinline__ u64 pk2(float lo, float hi) {
  u64 r; asm("mov.b64 %0, {%1, %2};" : "=l"(r) : "f"(lo), "f"(hi)); return r;
}
__device__ __forceinline__ u64 bc2(float v) { return pk2(v, v); }
__device__ __forceinline__ u64 fma2(u64 a, u64 b, u64 c) {
  u64 r; asm("fma.rn.f32x2 %0, %1, %2, %3;" : "=l"(r) : "l"(a), "l"(b), "l"(c)); return r;
}
__device__ __forceinline__ u64 mul2(u64 a, u64 b) {
  u64 r; asm("mul.rn.f32x2 %0, %1, %2;" : "=l"(r) : "l"(a), "l"(b)); return r;
}
__device__ __forceinline__ u64 add2(u64 a, u64 b) {
  u64 r; asm("add.rn.f32x2 %0, %1, %2;" : "=l"(r) : "l"(a), "l"(b)); return r;
}
__device__ __forceinline__ void up2(u64 v, float& lo, float& hi) {
  asm("mov.b64 {%0, %1}, %2;" : "=f"(lo), "=f"(hi) : "l"(v));
}
__device__ __forceinline__ float hsum2(u64 v) {
  float lo, hi; up2(v, lo, hi); return lo + hi;
}
__device__ __forceinline__ float leaky(float v) { return fmaxf(v, 0.01f * v); }

struct __align__(16) Smem {
  float adjT[EPB][ADJF];        // per e: [(n*13+m)*4 + ch]; reused as recon staging [k][n][m]
  float x[EPB][NN][DD];         // node features (reused for decoder temp)
  float w0t[NLAYERS][DD][DD];   // transposed: [l][d][o] = W0[l][o][d]
  float b0_[NLAYERS][DD];
  float w1t[NLAYERS][DD][DD];
  float b1_[NLAYERS][DD];
  float fc1t[DD][DD]; float fc1b_[DD];
  float fc2t[DD][DD]; float fc2b_[DD];
  float dect[NCH][DD][DD];      // [k][l2][d] = dec[k][d][l2]
  float decb_[NCH][DD];
  float wi[NN][DD];
  float bnia[NLAYERS][NN]; float bnib[NLAYERS][NN];
  float bnoa[NLAYERS][NN]; float bnob[NLAYERS][NN];
  float epsp[NLAYERS];
};

// outer-product matrix apply: acc[p][:] = bias + sum_d in[p][d] * wt[d][:]
// wt row is a warp-wide broadcast load shared by all EPT elements.
__device__ __forceinline__ void mat_apply(const float in[EPT][DD],
                                          const float* __restrict__ wt,
                                          const float* __restrict__ bias,
                                          u64 acc[EPT][8]) {
  const ulonglong2* bp = reinterpret_cast<const ulonglong2*>(bias);
  ulonglong2 bq0 = bp[0], bq1 = bp[1], bq2 = bp[2], bq3 = bp[3];
  #pragma unroll
  for (int p = 0; p < EPT; p++) {
    acc[p][0] = bq0.x; acc[p][1] = bq0.y; acc[p][2] = bq1.x; acc[p][3] = bq1.y;
    acc[p][4] = bq2.x; acc[p][5] = bq2.y; acc[p][6] = bq3.x; acc[p][7] = bq3.y;
  }
  #pragma unroll
  for (int d = 0; d < DD; d++) {
    const ulonglong2* wr = reinterpret_cast<const ulonglong2*>(wt + d * DD);
    ulonglong2 w0 = wr[0], w1 = wr[1], w2 = wr[2], w3 = wr[3];
    #pragma unroll
    for (int p = 0; p < EPT; p++) {
      u64 ad = bc2(in[p][d]);
      acc[p][0] = fma2(ad, w0.x, acc[p][0]); acc[p][1] = fma2(ad, w0.y, acc[p][1]);
      acc[p][2] = fma2(ad, w1.x, acc[p][2]); acc[p][3] = fma2(ad, w1.y, acc[p][3]);
      acc[p][4] = fma2(ad, w2.x, acc[p][4]); acc[p][5] = fma2(ad, w2.y, acc[p][5]);
      acc[p][6] = fma2(ad, w3.x, acc[p][6]); acc[p][7] = fma2(ad, w3.y, acc[p][7]);
    }
  }
}

extern "C" __global__ void __launch_bounds__(NTHREADS, 2)
vae_kernel(const float* __restrict__ g_adj, const float* __restrict__ g_wi,
           const float* __restrict__ g_eps,
           const float* __restrict__ g_w0, const float* __restrict__ g_b0,
           const float* __restrict__ g_w1, const float* __restrict__ g_b1,
           const float* __restrict__ g_big, const float* __restrict__ g_bib,
           const float* __restrict__ g_bim, const float* __restrict__ g_biv,
           const float* __restrict__ g_bog, const float* __restrict__ g_bob,
           const float* __restrict__ g_bom, const float* __restrict__ g_bov,
           const float* __restrict__ g_fc1w, const float* __restrict__ g_fc1b,
           const float* __restrict__ g_fc2w, const float* __restrict__ g_fc2b,
           const float* __restrict__ g_decw, const float* __restrict__ g_decb,
           float* __restrict__ o_recon, float* __restrict__ o_mu,
           float* __restrict__ o_lv, int Btot)
{
  extern __shared__ unsigned char smem_raw[];
  Smem& s = *reinterpret_cast<Smem*>(smem_raw);
  const int tid = threadIdx.x;

  const int b0blk = blockIdx.x * EPB;
  const int nelem = (Btot - b0blk) < EPB ? (Btot - b0blk) : EPB;

  // ---- stage adjacency transposed to [e][(n*13+m)*4+ch] ----
  {
    const float* src = g_adj + (size_t)b0blk * ADJF;
    const int cnt = nelem * ADJF;
    for (int i = tid; i < cnt; i += NTHREADS) {
      int e = i / ADJF, r = i - e * ADJF;
      int ch = r / (NN * NN), rr = r - ch * (NN * NN);
      int nr = rr / NN, mr = rr - nr * NN;
      s.adjT[e][(nr * NN + mr) * NCH + ch] = src[i];
    }
  }
  // ---- stage transposed weights ----
  for (int i = tid; i < NLAYERS * DD * DD; i += NTHREADS) {
    int l = i >> 8, r = i & 255, o = r >> 4, d = r & 15;
    int dst = (l << 8) + (d << 4) + o;
    (&s.w0t[0][0][0])[dst] = g_w0[i];
    (&s.w1t[0][0][0])[dst] = g_w1[i];
    (&s.dect[0][0][0])[dst] = g_decw[i];   // l plays role of k
  }
  for (int i = tid; i < DD * DD; i += NTHREADS) {
    int o = i >> 4, d = i & 15;
    s.fc1t[d][o] = g_fc1w[i];
    s.fc2t[d][o] = g_fc2w[i];
  }
  for (int i = tid; i < NLAYERS * DD; i += NTHREADS) {
    (&s.b0_[0][0])[i]   = g_b0[i];
    (&s.b1_[0][0])[i]   = g_b1[i];
    (&s.decb_[0][0])[i] = g_decb[i];
  }
  if (tid < DD) { s.fc1b_[tid] = g_fc1b[tid]; s.fc2b_[tid] = g_fc2b[tid]; }
  for (int i = tid; i < NN * DD; i += NTHREADS) (&s.wi[0][0])[i] = g_wi[i];
  if (tid < NLAYERS) s.epsp[tid] = g_eps[tid];
  for (int i = tid; i < NLAYERS * NN; i += NTHREADS) {
    float a = g_big[i] * rsqrtf(g_biv[i] + BN_EPS);
    (&s.bnia[0][0])[i] = a;
    (&s.bnib[0][0])[i] = g_bib[i] - g_bim[i] * a;
    float ao = g_bog[i] * rsqrtf(g_bov[i] + BN_EPS);
    (&s.bnoa[0][0])[i] = ao;
    (&s.bnob[0][0])[i] = g_bob[i] - g_bom[i] * ao;
  }
  __syncthreads();

  const int grp = tid >> 4;        // 8 groups of 16 lanes, each owns EPT elements
  const int n = tid & 15;          // node index; lanes 13..15 idle
  const bool act = (n < NN);
  const unsigned mask = (tid & 16) ? 0xFFFF0000u : 0x0000FFFFu;
  int es[EPT];
  #pragma unroll
  for (int p = 0; p < EPT; p++) es[p] = grp * EPT + p;

  float x[EPT][DD];
  // ---- initial embedding: x = (sum_ch adj) @ Wi ----
  if (act) {
    u64 xacc[EPT][8];
    #pragma unroll
    for (int p = 0; p < EPT; p++)
      #pragma unroll
      for (int j = 0; j < 8; j++) xacc[p][j] = 0ull;
    #pragma unroll
    for (int m = 0; m < NN; m++) {
      const ulonglong2* wm = reinterpret_cast<const ulonglong2*>(s.wi[m]);
      ulonglong2 wa = wm[0], wb = wm[1], wc = wm[2], wd = wm[3];
      #pragma unroll
      for (int p = 0; p < EPT; p++) {
        float4 a4 = *reinterpret_cast<const float4*>(
            &s.adjT[es[p]][(n * NN + m) * NCH]);
        u64 am = bc2((a4.x + a4.y) + (a4.z + a4.w));
        xacc[p][0] = fma2(am, wa.x, xacc[p][0]); xacc[p][1] = fma2(am, wa.y, xacc[p][1]);
        xacc[p][2] = fma2(am, wb.x, xacc[p][2]); xacc[p][3] = fma2(am, wb.y, xacc[p][3]);
        xacc[p][4] = fma2(am, wc.x, xacc[p][4]); xacc[p][5] = fma2(am, wc.y, xacc[p][5]);
        xacc[p][6] = fma2(am, wd.x, xacc[p][6]); xacc[p][7] = fma2(am, wd.y, xacc[p][7]);
      }
    }
    #pragma unroll
    for (int p = 0; p < EPT; p++) {
      #pragma unroll
      for (int j = 0; j < 8; j++) up2(xacc[p][j], x[p][2*j], x[p][2*j+1]);
      float4* xo = reinterpret_cast<float4*>(s.x[es[p]][n]);
      #pragma unroll
      for (int q = 0; q < 4; q++)
        xo[q] = make_float4(x[p][4*q], x[p][4*q+1], x[p][4*q+2], x[p][4*q+3]);
    }
  }
  __syncwarp(mask);

  // ---- GIN layers ----
  #pragma unroll 1
  for (int l = 0; l < NLAYERS; l++) {
    if (act) {
      u64 nb[EPT][8];
      #pragma unroll
      for (int p = 0; p < EPT; p++)
        #pragma unroll
        for (int j = 0; j < 8; j++) nb[p][j] = 0ull;
      #pragma unroll
      for (int m = 0; m < NN; m++) {
        #pragma unroll
        for (int p = 0; p < EPT; p++) {
          float4 a4 = *reinterpret_cast<const float4*>(
              &s.adjT[es[p]][(n * NN + m) * NCH]);
          const ulonglong2* xm = reinterpret_cast<const ulonglong2*>(s.x[es[p]][m]);
          ulonglong2 v0 = xm[0], v1 = xm[1], v2 = xm[2], v3 = xm[3];
          u64 a0 = bc2(a4.x), a1 = bc2(a4.y), a2 = bc2(a4.z), a3 = bc2(a4.w);
          nb[p][0] = fma2(a0, v0.x, nb[p][0]); nb[p][1] = fma2(a0, v0.y, nb[p][1]);
          nb[p][2] = fma2(a1, v1.x, nb[p][2]); nb[p][3] = fma2(a1, v1.y, nb[p][3]);
          nb[p][4] = fma2(a2, v2.x, nb[p][4]); nb[p][5] = fma2(a2, v2.y, nb[p][5]);
          nb[p][6] = fma2(a3, v3.x, nb[p][6]); nb[p][7] = fma2(a3, v3.y, nb[p][7]);
        }
      }
      const float ep = 1.f + s.epsp[l];
      float agg[EPT][DD];
      #pragma unroll
      for (int p = 0; p < EPT; p++)
        #pragma unroll
        for (int j = 0; j < 8; j++) {
          float lo, hi; up2(nb[p][j], lo, hi);
          agg[p][2*j]   = ep * x[p][2*j]   + lo;
          agg[p][2*j+1] = ep * x[p][2*j+1] + hi;
        }

      u64 acc[EPT][8];
      mat_apply(agg, &s.w0t[l][0][0], s.b0_[l], acc);
      const float ai = s.bnia[l][n], bi = s.bnib[l][n];
      #pragma unroll
      for (int p = 0; p < EPT; p++)
        #pragma unroll
        for (int j = 0; j < 8; j++) {
          float lo, hi; up2(acc[p][j], lo, hi);
          agg[p][2*j]   = leaky(lo * ai + bi);
          agg[p][2*j+1] = leaky(hi * ai + bi);
        }
      mat_apply(agg, &s.w1t[l][0][0], s.b1_[l], acc);
      const float ao = s.bnoa[l][n], bo = s.bnob[l][n];
      #pragma unroll
      for (int p = 0; p < EPT; p++)
        #pragma unroll
        for (int j = 0; j < 8; j++) {
          float lo, hi; up2(acc[p][j], lo, hi);
          x[p][2*j]   = leaky(lo * ao + bo);
          x[p][2*j+1] = leaky(hi * ao + bo);
        }
    }
    __syncwarp(mask);   // group reads of old x done
    if (act) {
      #pragma unroll
      for (int p = 0; p < EPT; p++) {
        float4* xo = reinterpret_cast<float4*>(s.x[es[p]][n]);
        #pragma unroll
        for (int q = 0; q < 4; q++)
          xo[q] = make_float4(x[p][4*q], x[p][4*q+1], x[p][4*q+2], x[p][4*q+3]);
      }
    }
    __syncwarp(mask);   // new x visible
  }

  // ---- mu / logvar heads ----
  float mu[EPT][DD];
  if (act) {
    u64 acc[EPT][8];
    mat_apply(x, &s.fc1t[0][0], s.fc1b_, acc);
    #pragma unroll
    for (int p = 0; p < EPT; p++) {
      #pragma unroll
      for (int j = 0; j < 8; j++) up2(acc[p][j], mu[p][2*j], mu[p][2*j+1]);
      if (es[p] < nelem) {
        size_t base = ((size_t)(b0blk + es[p]) * NN + n) * DD;
        float4* mo = reinterpret_cast<float4*>(o_mu + base);
        #pragma unroll
        for (int q = 0; q < 4; q++)
          mo[q] = make_float4(mu[p][4*q], mu[p][4*q+1], mu[p][4*q+2], mu[p][4*q+3]);
      }
    }
    mat_apply(x, &s.fc2t[0][0], s.fc2b_, acc);
    #pragma unroll
    for (int p = 0; p < EPT; p++) {
      if (es[p] < nelem) {
        float lv[DD];
        #pragma unroll
        for (int j = 0; j < 8; j++) up2(acc[p][j], lv[2*j], lv[2*j+1]);
        size_t base = ((size_t)(b0blk + es[p]) * NN + n) * DD;
        float4* lo = reinterpret_cast<float4*>(o_lv + base);
        #pragma unroll
        for (int q = 0; q < 4; q++)
          lo[q] = make_float4(lv[4*q], lv[4*q+1], lv[4*q+2], lv[4*q+3]);
      }
    }
  }

  // ---- decoder: recon[k][n][m] = relu(dot(t[n], t[m])), symmetric.
  //      Lane n computes pairs (n, (n+j)%13), j=0..6 — each unordered pair once.
  #pragma unroll 1
  for (int k = 0; k < NCH; k++) {
    u64 t2[EPT][8];
    if (act) {
      u64 acc[EPT][8];
      mat_apply(mu, &s.dect[k][0][0], s.decb_[k], acc);
      #pragma unroll
      for (int p = 0; p < EPT; p++)
        #pragma unroll
        for (int j = 0; j < 8; j++) t2[p][j] = acc[p][j];
    }
    __syncwarp(mask);   // previous k's reads of s.x done
    if (act) {
      #pragma unroll
      for (int p = 0; p < EPT; p++) {
        ulonglong2* xo = reinterpret_cast<ulonglong2*>(s.x[es[p]][n]);
        #pragma unroll
        for (int q = 0; q < 4; q++)
          xo[q] = make_ulonglong2(t2[p][2*q], t2[p][2*q+1]);
      }
    }
    __syncwarp(mask);
    if (act) {
      #pragma unroll
      for (int j = 0; j < 7; j++) {
        int m = n + j; if (m >= NN) m -= NN;
        #pragma unroll
        for (int p = 0; p < EPT; p++) {
          const ulonglong2* tm = reinterpret_cast<const ulonglong2*>(s.x[es[p]][m]);
          ulonglong2 v0 = tm[0], v1 = tm[1], v2 = tm[2], v3 = tm[3];
          u64 pa = mul2(t2[p][0], v0.x); pa = fma2(t2[p][1], v0.y, pa);
          pa = fma2(t2[p][2], v1.x, pa); pa = fma2(t2[p][3], v1.y, pa);
          u64 qa = mul2(t2[p][4], v2.x); qa = fma2(t2[p][5], v2.y, qa);
          qa = fma2(t2[p][6], v3.x, qa); qa = fma2(t2[p][7], v3.y, qa);
          float c = fmaxf(hsum2(add2(pa, qa)), 0.f);
          float* rE = &s.adjT[es[p]][k * (NN * NN)];
          rE[n * NN + m] = c;
          if (j) rE[m * NN + n] = c;
        }
      }
    }
  }

  // ---- coalesced recon store for the whole block ----
  __syncthreads();
  {
    const float4* src = reinterpret_cast<const float4*>(&s.adjT[0][0]);
    float4* dst = reinterpret_cast<float4*>(o_recon + (size_t)b0blk * ADJF);
    const int cnt = nelem * ADJF / 4;
    for (int i = tid; i < cnt; i += NTHREADS) dst[i] = src[i];
  }
}

extern "C" void kernel_launch(void* const* d_in, const int* in_sizes, int n_in,
                              void* d_out, int out_size) {
  const float* g_adj  = (const float*)d_in[0];
  const float* g_wi   = (const float*)d_in[1];
  const float* g_eps  = (const float*)d_in[2];
  const float* g_w0   = (const float*)d_in[3];
  const float* g_b0   = (const float*)d_in[4];
  const float* g_w1   = (const float*)d_in[5];
  const float* g_b1   = (const float*)d_in[6];
  const float* g_big  = (const float*)d_in[7];
  const float* g_bib  = (const float*)d_in[8];
  const float* g_bim  = (const float*)d_in[9];
  const float* g_biv  = (const float*)d_in[10];
  const float* g_bog  = (const float*)d_in[11];
  const float* g_bob  = (const float*)d_in[12];
  const float* g_bom  = (const float*)d_in[13];
  const float* g_bov  = (const float*)d_in[14];
  const float* g_fc1w = (const float*)d_in[15];
  const float* g_fc1b = (const float*)d_in[16];
  const float* g_fc2w = (const float*)d_in[17];
  const float* g_fc2b = (const float*)d_in[18];
  const float* g_decw = (const float*)d_in[19];
  const float* g_decb = (const float*)d_in[20];

  const int Btot = in_sizes[0] / ADJF;
  float* out = (float*)d_out;
  float* o_recon = out;
  float* o_mu = out + (size_t)Btot * ADJF;
  float* o_lv = o_mu + (size_t)Btot * NN * DD;

  cudaFuncSetAttribute((const void*)vae_kernel,
                       cudaFuncAttributeMaxDynamicSharedMemorySize,
                       (int)sizeof(Smem));
  int grid = (Btot + EPB - 1) / EPB;
  vae_kernel<<<grid, NTHREADS, sizeof(Smem)>>>(
      g_adj, g_wi, g_eps, g_w0, g_b0, g_w1, g_b1,
      g_big, g_bib, g_bim, g_biv, g_bog, g_bob, g_bom, g_bov,
      g_fc1w, g_fc1b, g_fc2w, g_fc2b, g_decw, g_decb,
      o_recon, o_mu, o_lv, Btot);
}

// round 10
// speedup vs baseline: 1.1997x; 1.1997x over previous
#include <cuda_runtime.h>
#include <cstddef>

#define NN 13
#define DD 16
#define EPB 16
#define NTHREADS 128
#define NLAYERS 4
#define NCH 4
#define BN_EPS 1e-5f
#define ADJF (NCH * NN * NN)   /* 676 floats per element */

typedef unsigned long long u64;

__device__ __forceinline__ u64 pk2(float lo, float hi) {
  u64 r; asm("mov.b64 %0, {%1, %2};" : "=l"(r) : "f"(lo), "f"(hi)); return r;
}
__device__ __forceinline__ u64 bc2(float v) { return pk2(v, v); }
__device__ __forceinline__ u64 fma2(u64 a, u64 b, u64 c) {
  u64 r; asm("fma.rn.f32x2 %0, %1, %2, %3;" : "=l"(r) : "l"(a), "l"(b), "l"(c)); return r;
}
__device__ __forceinline__ u64 mul2(u64 a, u64 b) {
  u64 r; asm("mul.rn.f32x2 %0, %1, %2;" : "=l"(r) : "l"(a), "l"(b)); return r;
}
__device__ __forceinline__ u64 add2(u64 a, u64 b) {
  u64 r; asm("add.rn.f32x2 %0, %1, %2;" : "=l"(r) : "l"(a), "l"(b)); return r;
}
__device__ __forceinline__ float hsum2(u64 v) {
  float lo, hi; asm("mov.b64 {%0, %1}, %2;" : "=f"(lo), "=f"(hi) : "l"(v));
  return lo + hi;
}
__device__ __forceinline__ float leaky(float v) { return fmaxf(v, 0.01f * v); }

struct __align__(16) Smem {
  float adjT[EPB][ADJF];        // [(n*13+m)*4+ch]; reused as recon staging [k][n][m]
  float x[EPB][NN][DD];         // node features (reused for decoder temp)
  float w0[NLAYERS][DD][DD];  float b0[NLAYERS][DD];
  float w1[NLAYERS][DD][DD];  float b1[NLAYERS][DD];
  float fc1[DD][DD]; float fc1b[DD];
  float fc2[DD][DD]; float fc2b[DD];
  float dec[NCH][DD][DD]; float decb[NCH][DD];
  float wi[NN][DD];
  float bnia[NLAYERS][NN]; float bnib[NLAYERS][NN];
  float bnoa[NLAYERS][NN]; float bnob[NLAYERS][NN];
  float epsp[NLAYERS];
};

// one weight-row load (4x LDS.128 broadcast) feeding TWO packed dot products
__device__ __forceinline__ void dot16x2(const u64* a, const u64* b,
                                        const float* row, float& ra, float& rb) {
  const ulonglong2* w = reinterpret_cast<const ulonglong2*>(row);
  ulonglong2 wa = w[0], wb = w[1], wc = w[2], wd = w[3];
  u64 pa = mul2(a[0], wa.x); pa = fma2(a[1], wa.y, pa);
  pa = fma2(a[2], wb.x, pa); pa = fma2(a[3], wb.y, pa);
  u64 qa = mul2(a[4], wc.x); qa = fma2(a[5], wc.y, qa);
  qa = fma2(a[6], wd.x, qa); qa = fma2(a[7], wd.y, qa);
  ra = hsum2(add2(pa, qa));
  u64 pb = mul2(b[0], wa.x); pb = fma2(b[1], wa.y, pb);
  pb = fma2(b[2], wb.x, pb); pb = fma2(b[3], wb.y, pb);
  u64 qb = mul2(b[4], wc.x); qb = fma2(b[5], wc.y, qb);
  qb = fma2(b[6], wd.x, qb); qb = fma2(b[7], wd.y, qb);
  rb = hsum2(add2(pb, qb));
}

extern "C" __global__ void __launch_bounds__(NTHREADS, 3)
vae_kernel(const float* __restrict__ g_adj, const float* __restrict__ g_wi,
           const float* __restrict__ g_eps,
           const float* __restrict__ g_w0, const float* __restrict__ g_b0,
           const float* __restrict__ g_w1, const float* __restrict__ g_b1,
           const float* __restrict__ g_big, const float* __restrict__ g_bib,
           const float* __restrict__ g_bim, const float* __restrict__ g_biv,
           const float* __restrict__ g_bog, const float* __restrict__ g_bob,
           const float* __restrict__ g_bom, const float* __restrict__ g_bov,
           const float* __restrict__ g_fc1w, const float* __restrict__ g_fc1b,
           const float* __restrict__ g_fc2w, const float* __restrict__ g_fc2b,
           const float* __restrict__ g_decw, const float* __restrict__ g_decb,
           float* __restrict__ o_recon, float* __restrict__ o_mu,
           float* __restrict__ o_lv, int Btot)
{
  extern __shared__ unsigned char smem_raw[];
  Smem& s = *reinterpret_cast<Smem*>(smem_raw);
  const int tid = threadIdx.x;

  const int b0blk = blockIdx.x * EPB;
  const int nelem = (Btot - b0blk) < EPB ? (Btot - b0blk) : EPB;

  // ---- stage adjacency channel-transposed: gather 4 coalesced scalar LDGs
  //      (one per channel) -> one STS.128 ----
  {
    const float* src = g_adj + (size_t)b0blk * ADJF;
    const int cnt = nelem * (NN * NN);    // 16*169 = 2704 float4 groups
    for (int i = tid; i < cnt; i += NTHREADS) {
      int e = i / (NN * NN), r = i - e * (NN * NN);
      const float* se = src + (size_t)e * ADJF + r;
      float4 v;
      v.x = se[0 * NN * NN]; v.y = se[1 * NN * NN];
      v.z = se[2 * NN * NN]; v.w = se[3 * NN * NN];
      *reinterpret_cast<float4*>(&s.adjT[e][r * 4]) = v;
    }
  }
  // ---- stage weights / biases ----
  {
    float4* dw0 = reinterpret_cast<float4*>(&s.w0[0][0][0]);
    float4* dw1 = reinterpret_cast<float4*>(&s.w1[0][0][0]);
    float4* ddc = reinterpret_cast<float4*>(&s.dec[0][0][0]);
    const float4* sw0 = reinterpret_cast<const float4*>(g_w0);
    const float4* sw1 = reinterpret_cast<const float4*>(g_w1);
    const float4* sdc = reinterpret_cast<const float4*>(g_decw);
    for (int i = tid; i < NLAYERS * DD * DD / 4; i += NTHREADS) {
      dw0[i] = sw0[i]; dw1[i] = sw1[i]; ddc[i] = sdc[i];
    }
    float4* df1 = reinterpret_cast<float4*>(&s.fc1[0][0]);
    float4* df2 = reinterpret_cast<float4*>(&s.fc2[0][0]);
    const float4* sf1 = reinterpret_cast<const float4*>(g_fc1w);
    const float4* sf2 = reinterpret_cast<const float4*>(g_fc2w);
    for (int i = tid; i < DD * DD / 4; i += NTHREADS) { df1[i] = sf1[i]; df2[i] = sf2[i]; }
  }
  for (int i = tid; i < NLAYERS * DD; i += NTHREADS) {
    (&s.b0[0][0])[i]   = g_b0[i];
    (&s.b1[0][0])[i]   = g_b1[i];
    (&s.decb[0][0])[i] = g_decb[i];
  }
  if (tid < DD) { s.fc1b[tid] = g_fc1b[tid]; s.fc2b[tid] = g_fc2b[tid]; }
  for (int i = tid; i < NN * DD; i += NTHREADS) (&s.wi[0][0])[i] = g_wi[i];
  if (tid < NLAYERS) s.epsp[tid] = g_eps[tid];
  for (int i = tid; i < NLAYERS * NN; i += NTHREADS) {
    float a = g_big[i] * rsqrtf(g_biv[i] + BN_EPS);
    (&s.bnia[0][0])[i] = a;
    (&s.bnib[0][0])[i] = g_bib[i] - g_bim[i] * a;
    float ao = g_bog[i] * rsqrtf(g_bov[i] + BN_EPS);
    (&s.bnoa[0][0])[i] = ao;
    (&s.bnob[0][0])[i] = g_bob[i] - g_bom[i] * ao;
  }
  __syncthreads();

  const int grp = tid >> 4;        // 8 groups, each owns TWO elements
  const int n = tid & 15;          // node index; lanes 13..15 idle
  const int e0 = grp * 2, e1 = grp * 2 + 1;
  const bool act = (n < NN);
  const unsigned mask = (tid & 16) ? 0xFFFF0000u : 0x0000FFFFu;
  const int b0g = b0blk + e0, b1g = b0blk + e1;

  const float* adjN0 = &s.adjT[e0][n * NN * 4];   // 13 float4s for this node
  const float* adjN1 = &s.adjT[e1][n * NN * 4];

  u64 xa[8], xb[8];
  // ---- initial embedding for both elements ----
  if (act) {
    #pragma unroll
    for (int j = 0; j < 8; j++) { xa[j] = 0ull; xb[j] = 0ull; }
    #pragma unroll
    for (int m = 0; m < NN; m++) {
      float4 a4 = *reinterpret_cast<const float4*>(adjN0 + m * 4);
      float4 c4 = *reinterpret_cast<const float4*>(adjN1 + m * 4);
      u64 ba = bc2((a4.x + a4.y) + (a4.z + a4.w));
      u64 bb = bc2((c4.x + c4.y) + (c4.z + c4.w));
      const ulonglong2* wm = reinterpret_cast<const ulonglong2*>(s.wi[m]);
      ulonglong2 wa = wm[0], wbq = wm[1], wc = wm[2], wd = wm[3];
      xa[0]=fma2(ba,wa.x,xa[0]); xa[1]=fma2(ba,wa.y,xa[1]);
      xa[2]=fma2(ba,wbq.x,xa[2]); xa[3]=fma2(ba,wbq.y,xa[3]);
      xa[4]=fma2(ba,wc.x,xa[4]); xa[5]=fma2(ba,wc.y,xa[5]);
      xa[6]=fma2(ba,wd.x,xa[6]); xa[7]=fma2(ba,wd.y,xa[7]);
      xb[0]=fma2(bb,wa.x,xb[0]); xb[1]=fma2(bb,wa.y,xb[1]);
      xb[2]=fma2(bb,wbq.x,xb[2]); xb[3]=fma2(bb,wbq.y,xb[3]);
      xb[4]=fma2(bb,wc.x,xb[4]); xb[5]=fma2(bb,wc.y,xb[5]);
      xb[6]=fma2(bb,wd.x,xb[6]); xb[7]=fma2(bb,wd.y,xb[7]);
    }
    ulonglong2* xo0 = reinterpret_cast<ulonglong2*>(s.x[e0][n]);
    ulonglong2* xo1 = reinterpret_cast<ulonglong2*>(s.x[e1][n]);
    #pragma unroll
    for (int q = 0; q < 4; q++) {
      xo0[q] = make_ulonglong2(xa[2*q], xa[2*q+1]);
      xo1[q] = make_ulonglong2(xb[2*q], xb[2*q+1]);
    }
  }
  __syncwarp(mask);

  // ---- GIN layers ----
  #pragma unroll 1
  for (int l = 0; l < NLAYERS; l++) {
    if (act) {
      u64 na[8], nb[8];
      #pragma unroll
      for (int j = 0; j < 8; j++) { na[j] = 0ull; nb[j] = 0ull; }
      #pragma unroll
      for (int m = 0; m < NN; m++) {
        float4 a4 = *reinterpret_cast<const float4*>(adjN0 + m * 4);
        u64 a0 = bc2(a4.x), a1 = bc2(a4.y), a2 = bc2(a4.z), a3 = bc2(a4.w);
        const ulonglong2* xm0 = reinterpret_cast<const ulonglong2*>(s.x[e0][m]);
        ulonglong2 v0 = xm0[0], v1 = xm0[1], v2 = xm0[2], v3 = xm0[3];
        na[0]=fma2(a0,v0.x,na[0]); na[1]=fma2(a0,v0.y,na[1]);
        na[2]=fma2(a1,v1.x,na[2]); na[3]=fma2(a1,v1.y,na[3]);
        na[4]=fma2(a2,v2.x,na[4]); na[5]=fma2(a2,v2.y,na[5]);
        na[6]=fma2(a3,v3.x,na[6]); na[7]=fma2(a3,v3.y,na[7]);
        float4 c4 = *reinterpret_cast<const float4*>(adjN1 + m * 4);
        u64 c0 = bc2(c4.x), c1 = bc2(c4.y), c2 = bc2(c4.z), c3 = bc2(c4.w);
        const ulonglong2* xm1 = reinterpret_cast<const ulonglong2*>(s.x[e1][m]);
        ulonglong2 u0 = xm1[0], u1 = xm1[1], u2 = xm1[2], u3 = xm1[3];
        nb[0]=fma2(c0,u0.x,nb[0]); nb[1]=fma2(c0,u0.y,nb[1]);
        nb[2]=fma2(c1,u1.x,nb[2]); nb[3]=fma2(c1,u1.y,nb[3]);
        nb[4]=fma2(c2,u2.x,nb[4]); nb[5]=fma2(c2,u2.y,nb[5]);
        nb[6]=fma2(c3,u3.x,nb[6]); nb[7]=fma2(c3,u3.y,nb[7]);
      }
      u64 ep = bc2(1.f + s.epsp[l]);
      #pragma unroll
      for (int j = 0; j < 8; j++) {
        na[j] = fma2(ep, xa[j], na[j]);
        nb[j] = fma2(ep, xb[j], nb[j]);
      }
      const float ai = s.bnia[l][n], bi = s.bnib[l][n];
      float ha[DD], hb[DD];
      #pragma unroll
      for (int o = 0; o < DD; o++) {
        float da, db;
        dot16x2(na, nb, s.w0[l][o], da, db);
        float bias = s.b0[l][o];
        ha[o] = leaky((da + bias) * ai + bi);
        hb[o] = leaky((db + bias) * ai + bi);
      }
      u64 h2a[8], h2b[8];
      #pragma unroll
      for (int j = 0; j < 8; j++) {
        h2a[j] = pk2(ha[2*j], ha[2*j+1]);
        h2b[j] = pk2(hb[2*j], hb[2*j+1]);
      }
      const float ao = s.bnoa[l][n], bo = s.bnob[l][n];
      float sxa[DD], sxb[DD];
      #pragma unroll
      for (int o = 0; o < DD; o++) {
        float da, db;
        dot16x2(h2a, h2b, s.w1[l][o], da, db);
        float bias = s.b1[l][o];
        sxa[o] = leaky((da + bias) * ao + bo);
        sxb[o] = leaky((db + bias) * ao + bo);
      }
      #pragma unroll
      for (int j = 0; j < 8; j++) {
        xa[j] = pk2(sxa[2*j], sxa[2*j+1]);
        xb[j] = pk2(sxb[2*j], sxb[2*j+1]);
      }
    }
    __syncwarp(mask);
    if (act) {
      ulonglong2* xo0 = reinterpret_cast<ulonglong2*>(s.x[e0][n]);
      ulonglong2* xo1 = reinterpret_cast<ulonglong2*>(s.x[e1][n]);
      #pragma unroll
      for (int q = 0; q < 4; q++) {
        xo0[q] = make_ulonglong2(xa[2*q], xa[2*q+1]);
        xo1[q] = make_ulonglong2(xb[2*q], xb[2*q+1]);
      }
    }
    __syncwarp(mask);
  }

  // ---- mu / logvar heads ----
  u64 mua[8], mub[8];
  if (act) {
    float ma[DD], mb[DD], la[DD], lb[DD];
    #pragma unroll
    for (int o = 0; o < DD; o++) {
      float da, db;
      dot16x2(xa, xb, s.fc1[o], da, db);
      ma[o] = da + s.fc1b[o]; mb[o] = db + s.fc1b[o];
      dot16x2(xa, xb, s.fc2[o], da, db);
      la[o] = da + s.fc2b[o]; lb[o] = db + s.fc2b[o];
    }
    #pragma unroll
    for (int j = 0; j < 8; j++) {
      mua[j] = pk2(ma[2*j], ma[2*j+1]);
      mub[j] = pk2(mb[2*j], mb[2*j+1]);
    }
    if (e0 < nelem) {
      size_t base = ((size_t)b0g * NN + n) * DD;
      float4* mo = reinterpret_cast<float4*>(o_mu + base);
      float4* lo = reinterpret_cast<float4*>(o_lv + base);
      #pragma unroll
      for (int q = 0; q < 4; q++) {
        mo[q] = make_float4(ma[4*q], ma[4*q+1], ma[4*q+2], ma[4*q+3]);
        lo[q] = make_float4(la[4*q], la[4*q+1], la[4*q+2], la[4*q+3]);
      }
    }
    if (e1 < nelem) {
      size_t base = ((size_t)b1g * NN + n) * DD;
      float4* mo = reinterpret_cast<float4*>(o_mu + base);
      float4* lo = reinterpret_cast<float4*>(o_lv + base);
      #pragma unroll
      for (int q = 0; q < 4; q++) {
        mo[q] = make_float4(mb[4*q], mb[4*q+1], mb[4*q+2], mb[4*q+3]);
        lo[q] = make_float4(lb[4*q], lb[4*q+1], lb[4*q+2], lb[4*q+3]);
      }
    }
  }

  // ---- decoder: recon[k] = relu(T T^T) is SYMMETRIC. Lane n computes pairs
  //      (n, (n+j)%13) for j=0..6 (each unordered pair once; 13 odd) and writes
  //      both mirror entries into the (dead) adjT staging region. ----
  float* recon0 = &s.adjT[e0][0];
  float* recon1 = &s.adjT[e1][0];
  #pragma unroll 1
  for (int k = 0; k < NCH; k++) {
    u64 ta[8], tb[8];
    if (act) {
      float va[DD], vb[DD];
      #pragma unroll
      for (int d = 0; d < DD; d++) {
        float da, db;
        dot16x2(mua, mub, s.dec[k][d], da, db);
        float bias = s.decb[k][d];
        va[d] = da + bias; vb[d] = db + bias;
      }
      #pragma unroll
      for (int j = 0; j < 8; j++) {
        ta[j] = pk2(va[2*j], va[2*j+1]);
        tb[j] = pk2(vb[2*j], vb[2*j+1]);
      }
    }
    __syncwarp(mask);
    if (act) {
      ulonglong2* xo0 = reinterpret_cast<ulonglong2*>(s.x[e0][n]);
      ulonglong2* xo1 = reinterpret_cast<ulonglong2*>(s.x[e1][n]);
      #pragma unroll
      for (int q = 0; q < 4; q++) {
        xo0[q] = make_ulonglong2(ta[2*q], ta[2*q+1]);
        xo1[q] = make_ulonglong2(tb[2*q], tb[2*q+1]);
      }
    }
    __syncwarp(mask);
    if (act) {
      float* rp0 = recon0 + k * (NN * NN);
      float* rp1 = recon1 + k * (NN * NN);
      #pragma unroll
      for (int j = 0; j < 7; j++) {
        int m = n + j; if (m >= NN) m -= NN;
        const ulonglong2* tm0 = reinterpret_cast<const ulonglong2*>(s.x[e0][m]);
        ulonglong2 v0 = tm0[0], v1 = tm0[1], v2 = tm0[2], v3 = tm0[3];
        u64 p = mul2(ta[0], v0.x); p = fma2(ta[1], v0.y, p);
        p = fma2(ta[2], v1.x, p);  p = fma2(ta[3], v1.y, p);
        u64 q = mul2(ta[4], v2.x); q = fma2(ta[5], v2.y, q);
        q = fma2(ta[6], v3.x, q);  q = fma2(ta[7], v3.y, q);
        float c0v = fmaxf(hsum2(add2(p, q)), 0.f);
        rp0[n * NN + m] = c0v;
        if (j) rp0[m * NN + n] = c0v;
        const ulonglong2* tm1 = reinterpret_cast<const ulonglong2*>(s.x[e1][m]);
        ulonglong2 u0 = tm1[0], u1 = tm1[1], u2 = tm1[2], u3 = tm1[3];
        u64 pb = mul2(tb[0], u0.x); pb = fma2(tb[1], u0.y, pb);
        pb = fma2(tb[2], u1.x, pb); pb = fma2(tb[3], u1.y, pb);
        u64 qb = mul2(tb[4], u2.x); qb = fma2(tb[5], u2.y, qb);
        qb = fma2(tb[6], u3.x, qb); qb = fma2(tb[7], u3.y, qb);
        float c1v = fmaxf(hsum2(add2(pb, qb)), 0.f);
        rp1[n * NN + m] = c1v;
        if (j) rp1[m * NN + n] = c1v;
      }
    }
  }

  // ---- coalesced recon store for the whole block ----
  __syncthreads();
  {
    const float4* src = reinterpret_cast<const float4*>(&s.adjT[0][0]);
    float4* dst = reinterpret_cast<float4*>(o_recon + (size_t)b0blk * ADJF);
    const int cnt = nelem * ADJF / 4;
    for (int i = tid; i < cnt; i += NTHREADS) dst[i] = src[i];
  }
}

extern "C" void kernel_launch(void* const* d_in, const int* in_sizes, int n_in,
                              void* d_out, int out_size) {
  const float* g_adj  = (const float*)d_in[0];
  const float* g_wi   = (const float*)d_in[1];
  const float* g_eps  = (const float*)d_in[2];
  const float* g_w0   = (const float*)d_in[3];
  const float* g_b0   = (const float*)d_in[4];
  const float* g_w1   = (const float*)d_in[5];
  const float* g_b1   = (const float*)d_in[6];
  const float* g_big  = (const float*)d_in[7];
  const float* g_bib  = (const float*)d_in[8];
  const float* g_bim  = (const float*)d_in[9];
  const float* g_biv  = (const float*)d_in[10];
  const float* g_bog  = (const float*)d_in[11];
  const float* g_bob  = (const float*)d_in[12];
  const float* g_bom  = (const float*)d_in[13];
  const float* g_bov  = (const float*)d_in[14];
  const float* g_fc1w = (const float*)d_in[15];
  const float* g_fc1b = (const float*)d_in[16];
  const float* g_fc2w = (const float*)d_in[17];
  const float* g_fc2b = (const float*)d_in[18];
  const float* g_decw = (const float*)d_in[19];
  const float* g_decb = (const float*)d_in[20];

  const int Btot = in_sizes[0] / ADJF;
  float* out = (float*)d_out;
  float* o_recon = out;
  float* o_mu = out + (size_t)Btot * ADJF;
  float* o_lv = o_mu + (size_t)Btot * NN * DD;

  cudaFuncSetAttribute((const void*)vae_kernel,
                       cudaFuncAttributeMaxDynamicSharedMemorySize,
                       (int)sizeof(Smem));
  int grid = (Btot + EPB - 1) / EPB;
  vae_kernel<<<grid, NTHREADS, sizeof(Smem)>>>(
      g_adj, g_wi, g_eps, g_w0, g_b0, g_w1, g_b1,
      g_big, g_bib, g_bim, g_biv, g_bog, g_bob, g_bom, g_bov,
      g_fc1w, g_fc1b, g_fc2w, g_fc2b, g_decw, g_decb,
      o_recon, o_mu, o_lv, Btot);
}